// round 15
// baseline (speedup 1.0000x reference)
#include <cuda_runtime.h>
#include <stdint.h>

// Resolutions: floor(16 * growth^i) replicating numpy's float64 pipeline.
// Level 15: 16*growth^15 lands just below 4096 in float64 -> floor = 4095.
__constant__ float c_res[16] = {
    16.f, 23.f, 33.f, 48.f, 70.f, 101.f, 147.f, 212.f,
    307.f, 445.f, 645.f, 933.f, 1351.f, 1955.f, 2830.f, 4095.f
};

#define HG_P2 2654435761u
#define HG_P3 805459861u
#define HG_MASK 0x7FFFFu   // T-1, T = 2^19

// ---- Corner-blocked duplicate tables for levels 0..4 ----
#define DUP_R0 16
#define DUP_R1 23
#define DUP_R2 33
#define DUP_R3 48
#define DUP_R4 70
#define DUP_N0 (16*16*16)
#define DUP_N1 (23*23*23)
#define DUP_N2 (33*33*33)
#define DUP_N3 (48*48*48)
#define DUP_N4 (70*70*70)
#define DUP_OFF0 0
#define DUP_OFF1 (DUP_OFF0 + DUP_N0)      // 4096
#define DUP_OFF2 (DUP_OFF1 + DUP_N1)      // 16263
#define DUP_OFF3 (DUP_OFF2 + DUP_N2)      // 52200
#define DUP_OFF4 (DUP_OFF3 + DUP_N3)      // 162792
#define DUP_TOTAL (DUP_OFF4 + DUP_N4)     // 505792 cells (~32.4 MB)

#define BUILD_BLOCKS ((DUP_TOTAL + 255) / 256)   // 1976

__device__ __align__(64) float4 g_dup[DUP_TOTAL * 4];

__constant__ int c_dupR[5]    = {DUP_R0, DUP_R1, DUP_R2, DUP_R3, DUP_R4};
__constant__ int c_dupBase[5] = {DUP_OFF0, DUP_OFF1, DUP_OFF2, DUP_OFF3, DUP_OFF4};

// Shared bit-exact interpolation epilogue (reference order, strict RN, no FMA).
__device__ __forceinline__ float2 interp8(
    float2 f000, float2 f001, float2 f010, float2 f011,
    float2 f100, float2 f101, float2 f110, float2 f111,
    float wx, float wy, float wz)
{
    float wx0 = __fadd_rn(1.0f, -wx), wx1 = wx;
    float wy0 = __fadd_rn(1.0f, -wy), wy1 = wy;
    float wz0 = __fadd_rn(1.0f, -wz), wz1 = wz;

    float w000 = __fmul_rn(__fmul_rn(wx0, wy0), wz0);
    float w001 = __fmul_rn(__fmul_rn(wx0, wy0), wz1);
    float w010 = __fmul_rn(__fmul_rn(wx0, wy1), wz0);
    float w011 = __fmul_rn(__fmul_rn(wx0, wy1), wz1);
    float w100 = __fmul_rn(__fmul_rn(wx1, wy0), wz0);
    float w101 = __fmul_rn(__fmul_rn(wx1, wy0), wz1);
    float w110 = __fmul_rn(__fmul_rn(wx1, wy1), wz0);
    float w111 = __fmul_rn(__fmul_rn(wx1, wy1), wz1);

    float a0 = 0.0f, a1 = 0.0f;
    a0 = __fadd_rn(a0, __fmul_rn(f000.x, w000));  a1 = __fadd_rn(a1, __fmul_rn(f000.y, w000));
    a0 = __fadd_rn(a0, __fmul_rn(f001.x, w001));  a1 = __fadd_rn(a1, __fmul_rn(f001.y, w001));
    a0 = __fadd_rn(a0, __fmul_rn(f010.x, w010));  a1 = __fadd_rn(a1, __fmul_rn(f010.y, w010));
    a0 = __fadd_rn(a0, __fmul_rn(f011.x, w011));  a1 = __fadd_rn(a1, __fmul_rn(f011.y, w011));
    a0 = __fadd_rn(a0, __fmul_rn(f100.x, w100));  a1 = __fadd_rn(a1, __fmul_rn(f100.y, w100));
    a0 = __fadd_rn(a0, __fmul_rn(f101.x, w101));  a1 = __fadd_rn(a1, __fmul_rn(f101.y, w101));
    a0 = __fadd_rn(a0, __fmul_rn(f110.x, w110));  a1 = __fadd_rn(a1, __fmul_rn(f110.y, w110));
    a0 = __fadd_rn(a0, __fmul_rn(f111.x, w111));  a1 = __fadd_rn(a1, __fmul_rn(f111.y, w111));
    return make_float2(a0, a1);
}

// Scale/floor/frac, strict RN (bit-exact vs reference).
__device__ __forceinline__ void coords(
    float px, float py, float pz, float res,
    int& ix, int& iy, int& iz, float& wx, float& wy, float& wz)
{
    float sx = __fmul_rn(px, res);
    float sy = __fmul_rn(py, res);
    float sz = __fmul_rn(pz, res);
    float fx = floorf(sx);
    float fy = floorf(sy);
    float fz = floorf(sz);
    wx = __fadd_rn(sx, -fx);
    wy = __fadd_rn(sy, -fy);
    wz = __fadd_rn(sz, -fz);
    ix = (int)fx; iy = (int)fy; iz = (int)fz;
}

// ============ Kernel A: build (first BUILD_BLOCKS) + fine levels 5..15 ============
__global__ __launch_bounds__(256) void hashgrid_fine_kernel(
    const float* __restrict__ x,
    const float* __restrict__ table,
    float2* __restrict__ out,
    int n_points)
{
    if (blockIdx.x < BUILD_BLOCKS) {
        // ---- Build corner-blocked dup tables (runs concurrently with fine work) ----
        int id = blockIdx.x * 256 + threadIdx.x;
        if (id >= DUP_TOTAL) return;

        int lvl, R, c;
        if (id < DUP_OFF1)      { lvl = 0; R = DUP_R0; c = id; }
        else if (id < DUP_OFF2) { lvl = 1; R = DUP_R1; c = id - DUP_OFF1; }
        else if (id < DUP_OFF3) { lvl = 2; R = DUP_R2; c = id - DUP_OFF2; }
        else if (id < DUP_OFF4) { lvl = 3; R = DUP_R3; c = id - DUP_OFF3; }
        else                    { lvl = 4; R = DUP_R4; c = id - DUP_OFF4; }

        int iz = c % R;
        int r  = c / R;
        int iy = r % R;
        int ix = r / R;

        const float2* tab = (const float2*)table + ((uint32_t)lvl << 19);

        float2 v[8];
#pragma unroll
        for (int k = 0; k < 8; k++) {       // k = dx*4 + dy*2 + dz (ref order)
            int dx = k >> 2, dy = (k >> 1) & 1, dz = k & 1;
            uint32_t h = ((uint32_t)(ix + dx)
                        ^ ((uint32_t)(iy + dy) * HG_P2)
                        ^ ((uint32_t)(iz + dz) * HG_P3)) & HG_MASK;
            v[k] = __ldg(tab + h);
        }

        float4* dst = &g_dup[(size_t)id * 4];
        dst[0] = make_float4(v[0].x, v[0].y, v[1].x, v[1].y);
        dst[1] = make_float4(v[2].x, v[2].y, v[3].x, v[3].y);
        dst[2] = make_float4(v[4].x, v[4].y, v[5].x, v[5].y);
        dst[3] = make_float4(v[6].x, v[6].y, v[7].x, v[7].y);
        return;
    }

    // ---- Fine levels 5..15: pure hash-gather warps (no divergence) ----
    unsigned id = (blockIdx.x - BUILD_BLOCKS) * 256u + threadIdx.x;
    unsigned total = (unsigned)n_points * 11u;
    if (id >= total) return;

    unsigned p = id / 11u;                 // compiler: mul-hi
    int lvl    = 5 + (int)(id - p * 11u);

    float px = x[3 * p + 0];
    float py = x[3 * p + 1];
    float pz = x[3 * p + 2];

    int ix, iy, iz; float wx, wy, wz;
    coords(px, py, pz, c_res[lvl], ix, iy, iz, wx, wy, wz);

    uint32_t hx0 = (uint32_t)ix;
    uint32_t hx1 = hx0 + 1u;
    uint32_t hy0 = (uint32_t)iy * HG_P2;
    uint32_t hy1 = hy0 + HG_P2;
    uint32_t hz0 = (uint32_t)iz * HG_P3;
    uint32_t hz1 = hz0 + HG_P3;

    const float2* tab = (const float2*)table + ((uint32_t)lvl << 19);

    float2 f000 = __ldg(tab + ((hx0 ^ hy0 ^ hz0) & HG_MASK));
    float2 f001 = __ldg(tab + ((hx0 ^ hy0 ^ hz1) & HG_MASK));
    float2 f010 = __ldg(tab + ((hx0 ^ hy1 ^ hz0) & HG_MASK));
    float2 f011 = __ldg(tab + ((hx0 ^ hy1 ^ hz1) & HG_MASK));
    float2 f100 = __ldg(tab + ((hx1 ^ hy0 ^ hz0) & HG_MASK));
    float2 f101 = __ldg(tab + ((hx1 ^ hy0 ^ hz1) & HG_MASK));
    float2 f110 = __ldg(tab + ((hx1 ^ hy1 ^ hz0) & HG_MASK));
    float2 f111 = __ldg(tab + ((hx1 ^ hy1 ^ hz1) & HG_MASK));

    out[p * 16u + (unsigned)lvl] =
        interp8(f000, f001, f010, f011, f100, f101, f110, f111, wx, wy, wz);
}

// ============ Kernel C: dup levels 0..4 (pure LDG.128 warps) ============
__global__ __launch_bounds__(256) void hashgrid_dup_kernel(
    const float* __restrict__ x,
    float2* __restrict__ out,
    int n_points)
{
    unsigned id = blockIdx.x * 256u + threadIdx.x;
    unsigned total = (unsigned)n_points * 5u;
    if (id >= total) return;

    unsigned p = id / 5u;
    int lvl    = (int)(id - p * 5u);

    float px = x[3 * p + 0];
    float py = x[3 * p + 1];
    float pz = x[3 * p + 2];

    int ix, iy, iz; float wx, wy, wz;
    coords(px, py, pz, c_res[lvl], ix, iy, iz, wx, wy, wz);

    int dupR = c_dupR[lvl];
    int cell = (ix * dupR + iy) * dupR + iz;
    const float4* dp = &g_dup[(size_t)(c_dupBase[lvl] + cell) * 4];

    float4 q0 = __ldg(dp + 0);
    float4 q1 = __ldg(dp + 1);
    float4 q2 = __ldg(dp + 2);
    float4 q3 = __ldg(dp + 3);

    out[p * 16u + (unsigned)lvl] = interp8(
        make_float2(q0.x, q0.y), make_float2(q0.z, q0.w),
        make_float2(q1.x, q1.y), make_float2(q1.z, q1.w),
        make_float2(q2.x, q2.y), make_float2(q2.z, q2.w),
        make_float2(q3.x, q3.y), make_float2(q3.z, q3.w),
        wx, wy, wz);
}

extern "C" void kernel_launch(void* const* d_in, const int* in_sizes, int n_in,
                              void* d_out, int out_size)
{
    // Defensive input-order resolution: x (N*3) is smaller than table (T*L*F).
    const float* a = (const float*)d_in[0];
    const float* b = (const float*)d_in[1];
    int sa = in_sizes[0], sb = in_sizes[1];

    const float* x;
    const float* table;
    int x_elems;
    if (sa <= sb) { x = a; table = b; x_elems = sa; }
    else          { x = b; table = a; x_elems = sb; }

    float2* out = (float2*)d_out;
    int n_points = x_elems / 3;

    // Kernel A: build (first BUILD_BLOCKS blocks) + fine levels 5..15.
    unsigned fine_total  = (unsigned)n_points * 11u;
    unsigned fine_blocks = (fine_total + 255u) / 256u;
    hashgrid_fine_kernel<<<BUILD_BLOCKS + fine_blocks, 256>>>(x, table, out, n_points);

    // Kernel C: dup levels 0..4 (depends on build via stream order).
    unsigned dup_total  = (unsigned)n_points * 5u;
    unsigned dup_blocks = (dup_total + 255u) / 256u;
    hashgrid_dup_kernel<<<dup_blocks, 256>>>(x, out, n_points);
}

// round 16
// speedup vs baseline: 1.4358x; 1.4358x over previous
#include <cuda_runtime.h>
#include <stdint.h>

// Resolutions: floor(16 * growth^i) replicating numpy's float64 pipeline.
// Level 15: 16*growth^15 lands just below 4096 in float64 -> floor = 4095.
__constant__ float c_res[16] = {
    16.f, 23.f, 33.f, 48.f, 70.f, 101.f, 147.f, 212.f,
    307.f, 445.f, 645.f, 933.f, 1351.f, 1955.f, 2830.f, 4095.f
};

#define HG_P2 2654435761u
#define HG_P3 805459861u
#define HG_MASK 0x7FFFFu   // T-1, T = 2^19

// ---- Corner-blocked duplicate tables for levels 0..4 ----
// Level ℓ res R -> R^3 cells (ix = floor(x*R) <= R-1 since x < 1); per cell an
// aligned 64B block holding the 8 corner float2 features in reference order.
#define DUP_R0 16
#define DUP_R1 23
#define DUP_R2 33
#define DUP_R3 48
#define DUP_R4 70
#define DUP_N0 (16*16*16)                 // 4096
#define DUP_N1 (23*23*23)                 // 12167
#define DUP_N2 (33*33*33)                 // 35937
#define DUP_N3 (48*48*48)                 // 110592
#define DUP_N4 (70*70*70)                 // 343000
#define DUP_OFF0 0
#define DUP_OFF1 (DUP_OFF0 + DUP_N0)      // 4096
#define DUP_OFF2 (DUP_OFF1 + DUP_N1)      // 16263
#define DUP_OFF3 (DUP_OFF2 + DUP_N2)      // 52200
#define DUP_OFF4 (DUP_OFF3 + DUP_N3)      // 162792
#define DUP_TOTAL (DUP_OFF4 + DUP_N4)     // 505792 cells (~32.4 MB)

__device__ __align__(64) float4 g_dup[DUP_TOTAL * 4];

// cells-per-axis and cell-base-offset per level (0 where unused)
__constant__ int c_dupR[16]    = {DUP_R0,DUP_R1,DUP_R2,DUP_R3,DUP_R4,0,0,0,0,0,0,0,0,0,0,0};
__constant__ int c_dupBase[16] = {DUP_OFF0,DUP_OFF1,DUP_OFF2,DUP_OFF3,DUP_OFF4,0,0,0,0,0,0,0,0,0,0,0};

// Build kernel: one thread per cell; gather the cell's 8 hashed corners and
// write them as one contiguous 64B block. Pure copy -> bit-exact values.
__global__ __launch_bounds__(256) void build_dup_kernel(const float* __restrict__ table)
{
    int id = blockIdx.x * blockDim.x + threadIdx.x;
    if (id >= DUP_TOTAL) return;

    int lvl, R, c;
    if (id < DUP_OFF1)      { lvl = 0; R = DUP_R0; c = id; }
    else if (id < DUP_OFF2) { lvl = 1; R = DUP_R1; c = id - DUP_OFF1; }
    else if (id < DUP_OFF3) { lvl = 2; R = DUP_R2; c = id - DUP_OFF2; }
    else if (id < DUP_OFF4) { lvl = 3; R = DUP_R3; c = id - DUP_OFF3; }
    else                    { lvl = 4; R = DUP_R4; c = id - DUP_OFF4; }

    int iz = c % R;
    int r  = c / R;
    int iy = r % R;
    int ix = r / R;

    const float2* tab = (const float2*)table + ((uint32_t)lvl << 19);

    float2 v[8];
#pragma unroll
    for (int k = 0; k < 8; k++) {           // k = dx*4 + dy*2 + dz (ref order)
        int dx = k >> 2, dy = (k >> 1) & 1, dz = k & 1;
        uint32_t h = ((uint32_t)(ix + dx)
                    ^ ((uint32_t)(iy + dy) * HG_P2)
                    ^ ((uint32_t)(iz + dz) * HG_P3)) & HG_MASK;
        v[k] = __ldg(tab + h);
    }

    float4* dst = &g_dup[(size_t)id * 4];
    dst[0] = make_float4(v[0].x, v[0].y, v[1].x, v[1].y);
    dst[1] = make_float4(v[2].x, v[2].y, v[3].x, v[3].y);
    dst[2] = make_float4(v[4].x, v[4].y, v[5].x, v[5].y);
    dst[3] = make_float4(v[6].x, v[6].y, v[7].x, v[7].y);
}

__global__ __launch_bounds__(256) void hashgrid_kernel(
    const float* __restrict__ x,
    const float* __restrict__ table,
    float2* __restrict__ out,
    int n_points)
{
    int t = blockIdx.x * blockDim.x + threadIdx.x;
    int p   = t >> 4;       // point index
    int lvl = t & 15;       // level index
    if (p >= n_points) return;

    // 16 lanes share the same point: these loads broadcast within the warp.
    float px = x[3 * p + 0];
    float py = x[3 * p + 1];
    float pz = x[3 * p + 2];

    float res = c_res[lvl];
    // Strict IEEE float32 RN, no fma contraction — bit-exact vs reference.
    float sx = __fmul_rn(px, res);
    float sy = __fmul_rn(py, res);
    float sz = __fmul_rn(pz, res);
    float fx = floorf(sx);
    float fy = floorf(sy);
    float fz = floorf(sz);
    float wx = __fadd_rn(sx, -fx);
    float wy = __fadd_rn(sy, -fy);
    float wz = __fadd_rn(sz, -fz);

    int ix = (int)fx;
    int iy = (int)fy;
    int iz = (int)fz;

    float2 f000, f001, f010, f011, f100, f101, f110, f111;

    int dupR = c_dupR[lvl];
    if (dupR != 0) {
        // Levels 0..4: one contiguous 64B cell block (2 sectors, 4 wavefronts)
        // instead of 8 random 8B gathers (8 sectors, 8 wavefronts).
        int cell = (ix * dupR + iy) * dupR + iz;
        const float4* dp = &g_dup[(size_t)(c_dupBase[lvl] + cell) * 4];
        float4 q0 = __ldg(dp + 0);
        float4 q1 = __ldg(dp + 1);
        float4 q2 = __ldg(dp + 2);
        float4 q3 = __ldg(dp + 3);
        f000 = make_float2(q0.x, q0.y);  f001 = make_float2(q0.z, q0.w);
        f010 = make_float2(q1.x, q1.y);  f011 = make_float2(q1.z, q1.w);
        f100 = make_float2(q2.x, q2.y);  f101 = make_float2(q2.z, q2.w);
        f110 = make_float2(q3.x, q3.y);  f111 = make_float2(q3.z, q3.w);
    } else {
        // hash = ix ^ iy*P2 ^ iz*P3, masked to 19 bits. Exact integer math.
        uint32_t hx0 = (uint32_t)ix;
        uint32_t hx1 = hx0 + 1u;
        uint32_t hy0 = (uint32_t)iy * HG_P2;
        uint32_t hy1 = hy0 + HG_P2;
        uint32_t hz0 = (uint32_t)iz * HG_P3;
        uint32_t hz1 = hz0 + HG_P3;

        const float2* tab = (const float2*)table + ((uint32_t)lvl << 19);

        // 8 independent gathers back-to-back for MLP.
        f000 = __ldg(tab + ((hx0 ^ hy0 ^ hz0) & HG_MASK));
        f001 = __ldg(tab + ((hx0 ^ hy0 ^ hz1) & HG_MASK));
        f010 = __ldg(tab + ((hx0 ^ hy1 ^ hz0) & HG_MASK));
        f011 = __ldg(tab + ((hx0 ^ hy1 ^ hz1) & HG_MASK));
        f100 = __ldg(tab + ((hx1 ^ hy0 ^ hz0) & HG_MASK));
        f101 = __ldg(tab + ((hx1 ^ hy0 ^ hz1) & HG_MASK));
        f110 = __ldg(tab + ((hx1 ^ hy1 ^ hz0) & HG_MASK));
        f111 = __ldg(tab + ((hx1 ^ hy1 ^ hz1) & HG_MASK));
    }

    float wx0 = __fadd_rn(1.0f, -wx), wx1 = wx;
    float wy0 = __fadd_rn(1.0f, -wy), wy1 = wy;
    float wz0 = __fadd_rn(1.0f, -wz), wz1 = wz;

    // w = (x_term * y_term) * z_term, left-associated RN — matches reference.
    float w000 = __fmul_rn(__fmul_rn(wx0, wy0), wz0);
    float w001 = __fmul_rn(__fmul_rn(wx0, wy0), wz1);
    float w010 = __fmul_rn(__fmul_rn(wx0, wy1), wz0);
    float w011 = __fmul_rn(__fmul_rn(wx0, wy1), wz1);
    float w100 = __fmul_rn(__fmul_rn(wx1, wy0), wz0);
    float w101 = __fmul_rn(__fmul_rn(wx1, wy0), wz1);
    float w110 = __fmul_rn(__fmul_rn(wx1, wy1), wz0);
    float w111 = __fmul_rn(__fmul_rn(wx1, wy1), wz1);

    // Reference corner order, separate RN mul + add (no FMA) — bit-exact.
    float a0 = 0.0f, a1 = 0.0f;
    a0 = __fadd_rn(a0, __fmul_rn(f000.x, w000));  a1 = __fadd_rn(a1, __fmul_rn(f000.y, w000));
    a0 = __fadd_rn(a0, __fmul_rn(f001.x, w001));  a1 = __fadd_rn(a1, __fmul_rn(f001.y, w001));
    a0 = __fadd_rn(a0, __fmul_rn(f010.x, w010));  a1 = __fadd_rn(a1, __fmul_rn(f010.y, w010));
    a0 = __fadd_rn(a0, __fmul_rn(f011.x, w011));  a1 = __fadd_rn(a1, __fmul_rn(f011.y, w011));
    a0 = __fadd_rn(a0, __fmul_rn(f100.x, w100));  a1 = __fadd_rn(a1, __fmul_rn(f100.y, w100));
    a0 = __fadd_rn(a0, __fmul_rn(f101.x, w101));  a1 = __fadd_rn(a1, __fmul_rn(f101.y, w101));
    a0 = __fadd_rn(a0, __fmul_rn(f110.x, w110));  a1 = __fadd_rn(a1, __fmul_rn(f110.y, w110));
    a0 = __fadd_rn(a0, __fmul_rn(f111.x, w111));  a1 = __fadd_rn(a1, __fmul_rn(f111.y, w111));

    // 16 consecutive lanes (same point) write contiguous 128B: fully coalesced.
    out[p * 16 + lvl] = make_float2(a0, a1);
}

extern "C" void kernel_launch(void* const* d_in, const int* in_sizes, int n_in,
                              void* d_out, int out_size)
{
    // Defensive input-order resolution: x (N*3) is smaller than table (T*L*F).
    const float* a = (const float*)d_in[0];
    const float* b = (const float*)d_in[1];
    int sa = in_sizes[0], sb = in_sizes[1];

    const float* x;
    const float* table;
    int x_elems;
    if (sa <= sb) { x = a; table = b; x_elems = sa; }
    else          { x = b; table = a; x_elems = sb; }

    float2* out = (float2*)d_out;

    int n_points = x_elems / 3;
    int total = n_points * 16;
    int block = 256;

    // Pass 1: rebuild the corner-blocked dup tables (deterministic each call).
    build_dup_kernel<<<(DUP_TOTAL + block - 1) / block, block>>>(table);

    // Pass 2: main encode.
    hashgrid_kernel<<<(total + block - 1) / block, block>>>(x, table, out, n_points);
}

// round 17
// speedup vs baseline: 1.4647x; 1.0201x over previous
#include <cuda_runtime.h>
#include <stdint.h>

// Resolutions: floor(16 * growth^i) replicating numpy's float64 pipeline.
// Level 15: 16*growth^15 lands just below 4096 in float64 -> floor = 4095.
__constant__ float c_res[16] = {
    16.f, 23.f, 33.f, 48.f, 70.f, 101.f, 147.f, 212.f,
    307.f, 445.f, 645.f, 933.f, 1351.f, 1955.f, 2830.f, 4095.f
};

#define HG_P2 2654435761u
#define HG_P3 805459861u
#define HG_MASK 0x7FFFFu   // T-1, T = 2^19

// ---- Z-shared corner-blocked duplicate tables for levels 0..4 ----
// Block (ix,iy,zc), zc in [0,R], holds the 4 corners (dx,dy) at z=zc as one
// aligned 32B unit: {c00, c01, c10, c11} (cXY = corner (ix+X, iy+Y, zc)).
// A cell (ix,iy,iz) reads blocks zc=iz and zc=iz+1 -> contiguous 64B
// (2 sectors, 4x LDG.128), identical main-kernel cost to per-cell 64B blocks,
// but build gathers 4 (not 8) per block and the table is half the size.
#define DUP_R0 16
#define DUP_R1 23
#define DUP_R2 33
#define DUP_R3 48
#define DUP_R4 70
#define DUP_B0 (16*16*17)                 // 4352
#define DUP_B1 (23*23*24)                 // 12696
#define DUP_B2 (33*33*34)                 // 37026
#define DUP_B3 (48*48*49)                 // 112896
#define DUP_B4 (70*70*71)                 // 347900
#define DUP_OFF0 0
#define DUP_OFF1 (DUP_OFF0 + DUP_B0)      // 4352
#define DUP_OFF2 (DUP_OFF1 + DUP_B1)      // 17048
#define DUP_OFF3 (DUP_OFF2 + DUP_B2)      // 54074
#define DUP_OFF4 (DUP_OFF3 + DUP_B3)      // 166970
#define DUP_TOTAL (DUP_OFF4 + DUP_B4)     // 514870 blocks (~16.5 MB)

__device__ __align__(64) float4 g_dup[DUP_TOTAL * 2];   // 2 float4 per 32B block

// cells-per-axis and block-base-offset per level (0 where unused)
__constant__ int c_dupR[16]    = {DUP_R0,DUP_R1,DUP_R2,DUP_R3,DUP_R4,0,0,0,0,0,0,0,0,0,0,0};
__constant__ int c_dupBase[16] = {DUP_OFF0,DUP_OFF1,DUP_OFF2,DUP_OFF3,DUP_OFF4,0,0,0,0,0,0,0,0,0,0,0};

// Build kernel: one thread per 32B block; gather the 4 (dx,dy) corners at the
// block's z and write them contiguously. Pure copy -> bit-exact values.
__global__ __launch_bounds__(256) void build_dup_kernel(const float* __restrict__ table)
{
    int id = blockIdx.x * blockDim.x + threadIdx.x;
    if (id >= DUP_TOTAL) return;

    int lvl, R, c;
    if (id < DUP_OFF1)      { lvl = 0; R = DUP_R0; c = id; }
    else if (id < DUP_OFF2) { lvl = 1; R = DUP_R1; c = id - DUP_OFF1; }
    else if (id < DUP_OFF3) { lvl = 2; R = DUP_R2; c = id - DUP_OFF2; }
    else if (id < DUP_OFF4) { lvl = 3; R = DUP_R3; c = id - DUP_OFF3; }
    else                    { lvl = 4; R = DUP_R4; c = id - DUP_OFF4; }

    int Rp1 = R + 1;
    int zc = c % Rp1;
    int r  = c / Rp1;
    int iy = r % R;
    int ix = r / R;

    const float2* tab = (const float2*)table + ((uint32_t)lvl << 19);

    uint32_t hz = (uint32_t)zc * HG_P3;
    uint32_t hx0 = (uint32_t)ix;
    uint32_t hx1 = hx0 + 1u;
    uint32_t hy0 = (uint32_t)iy * HG_P2;
    uint32_t hy1 = hy0 + HG_P2;

    float2 c00 = __ldg(tab + ((hx0 ^ hy0 ^ hz) & HG_MASK));   // (ix  , iy  , zc)
    float2 c01 = __ldg(tab + ((hx0 ^ hy1 ^ hz) & HG_MASK));   // (ix  , iy+1, zc)
    float2 c10 = __ldg(tab + ((hx1 ^ hy0 ^ hz) & HG_MASK));   // (ix+1, iy  , zc)
    float2 c11 = __ldg(tab + ((hx1 ^ hy1 ^ hz) & HG_MASK));   // (ix+1, iy+1, zc)

    float4* dst = &g_dup[(size_t)id * 2];
    dst[0] = make_float4(c00.x, c00.y, c01.x, c01.y);
    dst[1] = make_float4(c10.x, c10.y, c11.x, c11.y);
}

__global__ __launch_bounds__(256) void hashgrid_kernel(
    const float* __restrict__ x,
    const float* __restrict__ table,
    float2* __restrict__ out,
    int n_points)
{
    int t = blockIdx.x * blockDim.x + threadIdx.x;
    int p   = t >> 4;       // point index
    int lvl = t & 15;       // level index
    if (p >= n_points) return;

    // 16 lanes share the same point: these loads broadcast within the warp.
    float px = x[3 * p + 0];
    float py = x[3 * p + 1];
    float pz = x[3 * p + 2];

    float res = c_res[lvl];
    // Strict IEEE float32 RN, no fma contraction — bit-exact vs reference.
    float sx = __fmul_rn(px, res);
    float sy = __fmul_rn(py, res);
    float sz = __fmul_rn(pz, res);
    float fx = floorf(sx);
    float fy = floorf(sy);
    float fz = floorf(sz);
    float wx = __fadd_rn(sx, -fx);
    float wy = __fadd_rn(sy, -fy);
    float wz = __fadd_rn(sz, -fz);

    int ix = (int)fx;
    int iy = (int)fy;
    int iz = (int)fz;

    float2 f000, f001, f010, f011, f100, f101, f110, f111;

    int dupR = c_dupR[lvl];
    if (dupR != 0) {
        // Levels 0..4: two contiguous 32B z-blocks (zc=iz, iz+1) = 64B
        // (2 sectors, 4 wavefronts) instead of 8 random 8B gathers.
        int blk = (ix * dupR + iy) * (dupR + 1) + iz;
        const float4* dp = &g_dup[(size_t)(c_dupBase[lvl] + blk) * 2];
        float4 q0 = __ldg(dp + 0);   // z=iz  : {c00, c01}
        float4 q1 = __ldg(dp + 1);   // z=iz  : {c10, c11}
        float4 q2 = __ldg(dp + 2);   // z=iz+1: {c00, c01}
        float4 q3 = __ldg(dp + 3);   // z=iz+1: {c10, c11}
        f000 = make_float2(q0.x, q0.y);  f010 = make_float2(q0.z, q0.w);
        f100 = make_float2(q1.x, q1.y);  f110 = make_float2(q1.z, q1.w);
        f001 = make_float2(q2.x, q2.y);  f011 = make_float2(q2.z, q2.w);
        f101 = make_float2(q3.x, q3.y);  f111 = make_float2(q3.z, q3.w);
    } else {
        // hash = ix ^ iy*P2 ^ iz*P3, masked to 19 bits. Exact integer math.
        uint32_t hx0 = (uint32_t)ix;
        uint32_t hx1 = hx0 + 1u;
        uint32_t hy0 = (uint32_t)iy * HG_P2;
        uint32_t hy1 = hy0 + HG_P2;
        uint32_t hz0 = (uint32_t)iz * HG_P3;
        uint32_t hz1 = hz0 + HG_P3;

        const float2* tab = (const float2*)table + ((uint32_t)lvl << 19);

        // 8 independent gathers back-to-back for MLP.
        f000 = __ldg(tab + ((hx0 ^ hy0 ^ hz0) & HG_MASK));
        f001 = __ldg(tab + ((hx0 ^ hy0 ^ hz1) & HG_MASK));
        f010 = __ldg(tab + ((hx0 ^ hy1 ^ hz0) & HG_MASK));
        f011 = __ldg(tab + ((hx0 ^ hy1 ^ hz1) & HG_MASK));
        f100 = __ldg(tab + ((hx1 ^ hy0 ^ hz0) & HG_MASK));
        f101 = __ldg(tab + ((hx1 ^ hy0 ^ hz1) & HG_MASK));
        f110 = __ldg(tab + ((hx1 ^ hy1 ^ hz0) & HG_MASK));
        f111 = __ldg(tab + ((hx1 ^ hy1 ^ hz1) & HG_MASK));
    }

    float wx0 = __fadd_rn(1.0f, -wx), wx1 = wx;
    float wy0 = __fadd_rn(1.0f, -wy), wy1 = wy;
    float wz0 = __fadd_rn(1.0f, -wz), wz1 = wz;

    // w = (x_term * y_term) * z_term, left-associated RN — matches reference.
    float w000 = __fmul_rn(__fmul_rn(wx0, wy0), wz0);
    float w001 = __fmul_rn(__fmul_rn(wx0, wy0), wz1);
    float w010 = __fmul_rn(__fmul_rn(wx0, wy1), wz0);
    float w011 = __fmul_rn(__fmul_rn(wx0, wy1), wz1);
    float w100 = __fmul_rn(__fmul_rn(wx1, wy0), wz0);
    float w101 = __fmul_rn(__fmul_rn(wx1, wy0), wz1);
    float w110 = __fmul_rn(__fmul_rn(wx1, wy1), wz0);
    float w111 = __fmul_rn(__fmul_rn(wx1, wy1), wz1);

    // Reference corner order, separate RN mul + add (no FMA) — bit-exact.
    float a0 = 0.0f, a1 = 0.0f;
    a0 = __fadd_rn(a0, __fmul_rn(f000.x, w000));  a1 = __fadd_rn(a1, __fmul_rn(f000.y, w000));
    a0 = __fadd_rn(a0, __fmul_rn(f001.x, w001));  a1 = __fadd_rn(a1, __fmul_rn(f001.y, w001));
    a0 = __fadd_rn(a0, __fmul_rn(f010.x, w010));  a1 = __fadd_rn(a1, __fmul_rn(f010.y, w010));
    a0 = __fadd_rn(a0, __fmul_rn(f011.x, w011));  a1 = __fadd_rn(a1, __fmul_rn(f011.y, w011));
    a0 = __fadd_rn(a0, __fmul_rn(f100.x, w100));  a1 = __fadd_rn(a1, __fmul_rn(f100.y, w100));
    a0 = __fadd_rn(a0, __fmul_rn(f101.x, w101));  a1 = __fadd_rn(a1, __fmul_rn(f101.y, w101));
    a0 = __fadd_rn(a0, __fmul_rn(f110.x, w110));  a1 = __fadd_rn(a1, __fmul_rn(f110.y, w110));
    a0 = __fadd_rn(a0, __fmul_rn(f111.x, w111));  a1 = __fadd_rn(a1, __fmul_rn(f111.y, w111));

    // 16 consecutive lanes (same point) write contiguous 128B: fully coalesced.
    out[p * 16 + lvl] = make_float2(a0, a1);
}

extern "C" void kernel_launch(void* const* d_in, const int* in_sizes, int n_in,
                              void* d_out, int out_size)
{
    // Defensive input-order resolution: x (N*3) is smaller than table (T*L*F).
    const float* a = (const float*)d_in[0];
    const float* b = (const float*)d_in[1];
    int sa = in_sizes[0], sb = in_sizes[1];

    const float* x;
    const float* table;
    int x_elems;
    if (sa <= sb) { x = a; table = b; x_elems = sa; }
    else          { x = b; table = a; x_elems = sb; }

    float2* out = (float2*)d_out;

    int n_points = x_elems / 3;
    int total = n_points * 16;
    int block = 256;

    // Pass 1: rebuild the z-shared dup tables (deterministic each call).
    build_dup_kernel<<<(DUP_TOTAL + block - 1) / block, block>>>(table);

    // Pass 2: main encode.
    hashgrid_kernel<<<(total + block - 1) / block, block>>>(x, table, out, n_points);
}